// round 9
// baseline (speedup 1.0000x reference)
#include <cuda_runtime.h>

// ---------------------------------------------------------------------------
// WEFPositionalEncoding: out[b,s,d] = x[b,s,d] + pos[s,d]
//   pos[0,:]      = cls_pos * pos_scale
//   pos[1+pt,:]   = LayerNorm(feats(pt) @ proj_w + proj_b) * pos_scale
//   feats(pt)     = tanh(alpha * {Re wp, Im wp, Re wp', Im wp'}) at z(pt)
//   wp/wp'        = truncated Weierstrass lattice sums over 624 points
// Shapes (fixed by setup): B=64, H=W=24, S=577, D=1024.
// ---------------------------------------------------------------------------

#define OMEGA1F 2.62205755429212f

// pos table scratch (S*D floats). 578*1024 to be safe.
__device__ float g_pos[578 * 1024];

__device__ __forceinline__ float clampf(float v, float lim) {
    return fminf(fmaxf(v, -lim), lim);
}

// One block per sequence position s (blockDim = 256).
// s == 0 : cls row. s >= 1 : patch row (pt = s-1).
__global__ void __launch_bounds__(256) pos_kernel(
    const float* __restrict__ las_p,   // log_alpha_scale [1]
    const float* __restrict__ al_p,    // alpha_learn     [1]
    const float* __restrict__ pw,      // proj_w [4, D]
    const float* __restrict__ pb,      // proj_b [D]
    const float* __restrict__ lg,      // ln_g   [D]
    const float* __restrict__ lb,      // ln_b   [D]
    const float* __restrict__ cls,     // cls_pos [D]
    const float* __restrict__ ps_p,    // pos_scale [1]
    int H, int W, int D)
{
    const int s   = blockIdx.x;
    const int tid = threadIdx.x;
    const float ps = ps_p[0];

    if (s == 0) {
        for (int d = tid; d < D; d += blockDim.x)
            g_pos[d] = cls[d] * ps;
        return;
    }

    const int pt  = s - 1;
    const int row = pt / W;
    const int col = pt % W;

    // omega_3' = clip(softplus(alpha_learn), 0.02, 8)
    const float al = al_p[0];
    float sp = (al > 20.0f) ? al : log1pf(expf(al));
    sp = fminf(fmaxf(sp, 0.02f), 8.0f);

    const float zr = ((col + 0.5f) / (float)W) * (2.0f * OMEGA1F) * 0.4f;
    const float zi = ((row + 0.5f) / (float)H) * (2.0f * sp) * 0.4f;

    // ---- lattice sum: 624 terms split over 256 threads ----
    float swr = 0.f, swi = 0.f, spr = 0.f, spi = 0.f;
    for (int l = tid; l < 624; l += 256) {
        const int l2 = (l < 312) ? l : l + 1;      // skip (m,n)=(0,0) at index 312
        const int m = l2 / 25 - 12;
        const int n = l2 % 25 - 12;
        const float wr = 2.0f * (float)m * OMEGA1F;
        const float wi = 2.0f * (float)n * OMEGA1F;

        const float dr = zr - wr, di = zi - wi;
        const float r2 = dr * dr + di * di;
        if (r2 > 2.25e-14f) {                      // |d| > NEAR (always true here)
            const float ir = 1.0f / r2;
            const float i2 = ir * ir;
            const float a = (dr * dr - di * di) * i2;   // Re 1/d^2
            const float b = (-2.0f * dr * di) * i2;     // Im 1/d^2

            // 1/w^2
            const float w2  = wr * wr + wi * wi;
            const float iw  = 1.0f / w2;
            const float iw2 = iw * iw;
            const float cwr = (wr * wr - wi * wi) * iw2;
            const float cwi = (-2.0f * wr * wi) * iw2;

            swr += clampf(a - cwr, 5000.0f);
            swi += clampf(b - cwi, 5000.0f);
            // -2/d^3 = -2 * (1/d^2) * (1/d),  1/d = (dr - i di) * ir
            spr += clampf(-2.0f * ir * (a * dr + b * di), 5000.0f);
            spi += clampf(-2.0f * ir * (b * dr - a * di), 5000.0f);
        }
    }

    __shared__ float4 sh[256];
    sh[tid] = make_float4(swr, swi, spr, spi);
    __syncthreads();
    #pragma unroll
    for (int off = 128; off > 0; off >>= 1) {
        if (tid < off) {
            float4 mv = sh[tid], ov = sh[tid + off];
            mv.x += ov.x; mv.y += ov.y; mv.z += ov.z; mv.w += ov.w;
            sh[tid] = mv;
        }
        __syncthreads();
    }

    __shared__ float f[4];
    if (tid == 0) {
        const float4 sm = sh[0];
        // singular terms at z
        const float r2 = zr * zr + zi * zi;
        const float ir = 1.0f / r2;
        const float i2 = ir * ir;
        const float a = (zr * zr - zi * zi) * i2;
        const float b = (-2.0f * zr * zi) * i2;
        const float wpre = clampf(a + sm.x, 10000.0f);
        const float wpim = clampf(b + sm.y, 10000.0f);
        const float ppre = clampf(-2.0f * ir * (a * zr + b * zi) + sm.z, 10000.0f);
        const float ppim = clampf(-2.0f * ir * (b * zr - a * zi) + sm.w, 10000.0f);

        const float alpha = fminf(fmaxf(expf(las_p[0]), 0.002f), 0.8f);
        f[0] = tanhf(alpha * wpre);
        f[1] = tanhf(alpha * wpim);
        f[2] = tanhf(alpha * ppre);
        f[3] = tanhf(alpha * ppim);
    }
    __syncthreads();

    // ---- projection (4 -> D) + LayerNorm over D ----
    const float f0 = f[0], f1 = f[1], f2 = f[2], f3 = f[3];
    float p[4];
    float sum = 0.f, sumsq = 0.f;
    #pragma unroll
    for (int k = 0; k < 4; k++) {
        const int d = tid + k * 256;
        const float v = f0 * pw[d] + f1 * pw[D + d] + f2 * pw[2 * D + d]
                      + f3 * pw[3 * D + d] + pb[d];
        p[k] = v;
        sum += v;
        sumsq += v * v;
    }
    __syncthreads();
    sh[tid].x = sum;
    sh[tid].y = sumsq;
    __syncthreads();
    #pragma unroll
    for (int off = 128; off > 0; off >>= 1) {
        if (tid < off) {
            sh[tid].x += sh[tid + off].x;
            sh[tid].y += sh[tid + off].y;
        }
        __syncthreads();
    }
    __shared__ float stats[2];
    if (tid == 0) {
        const float mu  = sh[0].x / (float)D;
        const float var = sh[0].y / (float)D - mu * mu;
        stats[0] = mu;
        stats[1] = rsqrtf(var + 1e-5f);
    }
    __syncthreads();
    const float mu = stats[0], rstd = stats[1];
    float* outrow = g_pos + (size_t)s * D;
    #pragma unroll
    for (int k = 0; k < 4; k++) {
        const int d = tid + k * 256;
        outrow[d] = ((p[k] - mu) * rstd * lg[d] + lb[d]) * ps;
    }
}

// Broadcast add: grid = (S, B), block = D/4 threads, one float4 per thread.
__global__ void __launch_bounds__(256) add_kernel(
    const float4* __restrict__ x, float4* __restrict__ out, int S, int Dq)
{
    const int s = blockIdx.x;
    const int b = blockIdx.y;
    const int j = s * Dq + threadIdx.x;               // index within one [S,D] image
    const size_t idx = (size_t)b * S * Dq + j;
    const float4* posv = (const float4*)g_pos;
    const float4 xv = x[idx];
    const float4 pv = posv[j];
    out[idx] = make_float4(xv.x + pv.x, xv.y + pv.y, xv.z + pv.z, xv.w + pv.w);
}

extern "C" void kernel_launch(void* const* d_in, const int* in_sizes, int n_in,
                              void* d_out, int out_size)
{
    // metadata order: x, h, w, log_alpha_scale, alpha_learn, proj_w, proj_b,
    //                 ln_g, ln_b, cls_pos, pos_scale
    int iX = 0, iLAS = 3, iAL = 4, iPW = 5, iPB = 6, iLG = 7, iLB = 8, iCLS = 9, iPS = 10;
    if (n_in == 9) {  // python-int h,w not materialized as inputs
        iLAS = 1; iAL = 2; iPW = 3; iPB = 4; iLG = 5; iLB = 6; iCLS = 7; iPS = 8;
    }

    const int H = 24, W = 24;
    const int S = H * W + 1;                       // 577
    const int D = in_sizes[iCLS];                  // 1024
    const long long total = (long long)in_sizes[iX];
    const int B = (int)(total / ((long long)S * D));
    const int Dq = D / 4;

    pos_kernel<<<S, 256>>>(
        (const float*)d_in[iLAS], (const float*)d_in[iAL],
        (const float*)d_in[iPW],  (const float*)d_in[iPB],
        (const float*)d_in[iLG],  (const float*)d_in[iLB],
        (const float*)d_in[iCLS], (const float*)d_in[iPS],
        H, W, D);

    dim3 grid(S, B);
    add_kernel<<<grid, Dq>>>((const float4*)d_in[iX], (float4*)d_out, S, Dq);
}

// round 10
// speedup vs baseline: 1.0441x; 1.0441x over previous
#include <cuda_runtime.h>

// ---------------------------------------------------------------------------
// WEFPositionalEncoding: out[b,s,d] = x[b,s,d] + pos[s,d]
// B=64, H=W=24, S=577, D=1024 (fixed by setup, but code stays generic-ish).
// ---------------------------------------------------------------------------

#define OMEGA1F 2.62205755429212f

__device__ float g_pos[578 * 1024];

__device__ __forceinline__ float clampf(float v, float lim) {
    return fminf(fmaxf(v, -lim), lim);
}

__device__ __forceinline__ float warp_sum(float v) {
    #pragma unroll
    for (int o = 16; o > 0; o >>= 1) v += __shfl_xor_sync(0xFFFFFFFFu, v, o);
    return v;
}

// One block per sequence position s (blockDim = 256).
__global__ void __launch_bounds__(256) pos_kernel(
    const float* __restrict__ las_p, const float* __restrict__ al_p,
    const float* __restrict__ pw,    const float* __restrict__ pb,
    const float* __restrict__ lg,    const float* __restrict__ lb,
    const float* __restrict__ cls,   const float* __restrict__ ps_p,
    int H, int W, int D)
{
    const int s    = blockIdx.x;
    const int tid  = threadIdx.x;
    const int wid  = tid >> 5;
    const int lane = tid & 31;
    const float ps = ps_p[0];

    if (s == 0) {
        for (int d = tid; d < D; d += blockDim.x)
            g_pos[d] = cls[d] * ps;
        return;
    }

    const int pt  = s - 1;
    const int row = pt / W;
    const int col = pt % W;

    const float al = al_p[0];
    float sp = (al > 20.0f) ? al : log1pf(expf(al));
    sp = fminf(fmaxf(sp, 0.02f), 8.0f);

    const float zr = ((col + 0.5f) / (float)W) * (2.0f * OMEGA1F) * 0.4f;
    const float zi = ((row + 0.5f) / (float)H) * (2.0f * sp) * 0.4f;

    // ---- lattice sum: 624 terms over 256 threads ----
    float swr = 0.f, swi = 0.f, spr = 0.f, spi = 0.f;
    for (int l = tid; l < 624; l += 256) {
        const int l2 = (l < 312) ? l : l + 1;      // skip (m,n)=(0,0)
        const int m = l2 / 25 - 12;
        const int n = l2 % 25 - 12;
        const float wr = 2.0f * (float)m * OMEGA1F;
        const float wi = 2.0f * (float)n * OMEGA1F;

        const float dr = zr - wr, di = zi - wi;
        const float r2 = dr * dr + di * di;
        const float ir = 1.0f / r2;
        const float i2 = ir * ir;
        const float a = (dr * dr - di * di) * i2;       // Re 1/d^2
        const float b = (-2.0f * dr * di) * i2;         // Im 1/d^2

        const float w2  = wr * wr + wi * wi;
        const float iw  = 1.0f / w2;
        const float iw2 = iw * iw;
        const float cwr = (wr * wr - wi * wi) * iw2;
        const float cwi = (-2.0f * wr * wi) * iw2;

        swr += clampf(a - cwr, 5000.0f);
        swi += clampf(b - cwi, 5000.0f);
        spr += clampf(-2.0f * ir * (a * dr + b * di), 5000.0f);
        spi += clampf(-2.0f * ir * (b * dr - a * di), 5000.0f);
    }

    // warp-shuffle reduction, then 8 warp partials via first warp
    swr = warp_sum(swr); swi = warp_sum(swi);
    spr = warp_sum(spr); spi = warp_sum(spi);

    __shared__ float4 wpart[8];
    __shared__ float f[4];
    if (lane == 0) wpart[wid] = make_float4(swr, swi, spr, spi);
    __syncthreads();
    if (tid == 0) {
        float4 sm = wpart[0];
        #pragma unroll
        for (int i = 1; i < 8; i++) {
            sm.x += wpart[i].x; sm.y += wpart[i].y;
            sm.z += wpart[i].z; sm.w += wpart[i].w;
        }
        // singular terms at z
        const float r2 = zr * zr + zi * zi;
        const float ir = 1.0f / r2;
        const float i2 = ir * ir;
        const float a = (zr * zr - zi * zi) * i2;
        const float b = (-2.0f * zr * zi) * i2;
        const float wpre = clampf(a + sm.x, 10000.0f);
        const float wpim = clampf(b + sm.y, 10000.0f);
        const float ppre = clampf(-2.0f * ir * (a * zr + b * zi) + sm.z, 10000.0f);
        const float ppim = clampf(-2.0f * ir * (b * zr - a * zi) + sm.w, 10000.0f);

        const float alpha = fminf(fmaxf(expf(las_p[0]), 0.002f), 0.8f);
        f[0] = tanhf(alpha * wpre);
        f[1] = tanhf(alpha * wpim);
        f[2] = tanhf(alpha * ppre);
        f[3] = tanhf(alpha * ppim);
    }
    __syncthreads();

    // ---- projection (4 -> D) + LayerNorm over D ----
    const float f0 = f[0], f1 = f[1], f2 = f[2], f3 = f[3];
    float p[4];
    float sum = 0.f, sumsq = 0.f;
    #pragma unroll
    for (int k = 0; k < 4; k++) {
        const int d = tid + k * 256;
        const float v = f0 * pw[d] + f1 * pw[D + d] + f2 * pw[2 * D + d]
                      + f3 * pw[3 * D + d] + pb[d];
        p[k] = v;
        sum += v;
        sumsq += v * v;
    }
    sum   = warp_sum(sum);
    sumsq = warp_sum(sumsq);

    __shared__ float2 mpart[8];
    __shared__ float stats[2];
    if (lane == 0) mpart[wid] = make_float2(sum, sumsq);
    __syncthreads();
    if (tid == 0) {
        float s1 = 0.f, s2 = 0.f;
        #pragma unroll
        for (int i = 0; i < 8; i++) { s1 += mpart[i].x; s2 += mpart[i].y; }
        const float mu  = s1 / (float)D;
        const float var = s2 / (float)D - mu * mu;
        stats[0] = mu;
        stats[1] = rsqrtf(var + 1e-5f);
    }
    __syncthreads();
    const float mu = stats[0], rstd = stats[1];
    float* outrow = g_pos + (size_t)s * D;
    #pragma unroll
    for (int k = 0; k < 4; k++) {
        const int d = tid + k * 256;
        outrow[d] = ((p[k] - mu) * rstd * lg[d] + lb[d]) * ps;
    }
}

// Broadcast add, 4 batch elements per block:
// grid = (S, ceil(B/4)), block = D/4. pos row loaded once, 4 independent
// x-loads issued back-to-back (MLP=4) then 4 stores.
__global__ void __launch_bounds__(256) add_kernel(
    const float4* __restrict__ x, float4* __restrict__ out,
    int S, int Dq, int B)
{
    const int s  = blockIdx.x;
    const int b0 = blockIdx.y * 4;
    const int j  = s * Dq + threadIdx.x;
    const float4 pv = ((const float4*)g_pos)[j];
    const size_t stride = (size_t)S * Dq;
    const size_t base = (size_t)b0 * stride + j;

    if (b0 + 4 <= B) {
        const float4 x0 = x[base];
        const float4 x1 = x[base + stride];
        const float4 x2 = x[base + 2 * stride];
        const float4 x3 = x[base + 3 * stride];
        out[base]              = make_float4(x0.x + pv.x, x0.y + pv.y, x0.z + pv.z, x0.w + pv.w);
        out[base + stride]     = make_float4(x1.x + pv.x, x1.y + pv.y, x1.z + pv.z, x1.w + pv.w);
        out[base + 2 * stride] = make_float4(x2.x + pv.x, x2.y + pv.y, x2.z + pv.z, x2.w + pv.w);
        out[base + 3 * stride] = make_float4(x3.x + pv.x, x3.y + pv.y, x3.z + pv.z, x3.w + pv.w);
    } else {
        for (int k = 0; k < B - b0; k++) {
            const float4 xv = x[base + (size_t)k * stride];
            out[base + (size_t)k * stride] =
                make_float4(xv.x + pv.x, xv.y + pv.y, xv.z + pv.z, xv.w + pv.w);
        }
    }
}

extern "C" void kernel_launch(void* const* d_in, const int* in_sizes, int n_in,
                              void* d_out, int out_size)
{
    int iX = 0, iLAS = 3, iAL = 4, iPW = 5, iPB = 6, iLG = 7, iLB = 8, iCLS = 9, iPS = 10;
    if (n_in == 9) {
        iLAS = 1; iAL = 2; iPW = 3; iPB = 4; iLG = 5; iLB = 6; iCLS = 7; iPS = 8;
    }

    const int H = 24, W = 24;
    const int S = H * W + 1;                       // 577
    const int D = in_sizes[iCLS];                  // 1024
    const long long total = (long long)in_sizes[iX];
    const int B = (int)(total / ((long long)S * D));
    const int Dq = D / 4;

    pos_kernel<<<S, 256>>>(
        (const float*)d_in[iLAS], (const float*)d_in[iAL],
        (const float*)d_in[iPW],  (const float*)d_in[iPB],
        (const float*)d_in[iLG],  (const float*)d_in[iLB],
        (const float*)d_in[iCLS], (const float*)d_in[iPS],
        H, W, D);

    dim3 grid(S, (B + 3) / 4);
    add_kernel<<<grid, Dq>>>((const float4*)d_in[iX], (float4*)d_out, S, Dq, B);
}